// round 1
// baseline (speedup 1.0000x reference)
#include <cuda_runtime.h>
#include <math.h>

#define N_PATCH 676
#define NPAD    704
#define D       384
#define M       200000
#define MPAD    200064
#define TN      64
#define TM      128
#define KB      32
#define NKT     12        // 384/32
#define NBX     11        // ceil(676/64)
#define MBY     1563      // ceil(200000/128)
#define IMG     224
#define KS      33
#define RAD     16

// ---------------- device scratch (no allocations allowed) ----------------
__device__ float g_patchN[NPAD * D];     // normalized patch, zero-padded rows
__device__ float g_pn[NPAD];             // ||p||^2 of normalized rows
__device__ float g_ln[MPAD];             // ||lib_m||^2 (padded rows = 1e30)
__device__ float g_pv[(size_t)NPAD * MBY];  // per-(n, m-block) partial min of ln-2dot
__device__ int   g_pi[(size_t)NPAD * MBY];  // corresponding argmin (global m)
__device__ float g_minval[N_PATCH];
__device__ int   g_minidx[N_PATCH];
__device__ float g_dstar[M];
__device__ float g_rmap[IMG * IMG];
__device__ float g_tmap[IMG * IMG];
__device__ float g_kern[KS];
__device__ int   g_sidx;
__device__ int   g_mstar;
__device__ float g_sstar;
__device__ float g_msn;
__device__ int   g_nn[5];

__device__ __forceinline__ bool lt_vi(float v1, int i1, float v2, int i2) {
    return (v1 < v2) || (v1 == v2 && i1 < i2);
}

// ---------------- 1) normalize patch rows, compute pn ----------------
__global__ void prep_kernel(const float* __restrict__ patch) {
    int n = blockIdx.x, t = threadIdx.x;   // 128 threads
    __shared__ float red[4];
    __shared__ float bcast;
    if (n >= N_PATCH) {
        for (int c = t; c < D; c += 128) g_patchN[(size_t)n * D + c] = 0.f;
        if (t == 0) g_pn[n] = 0.f;
        return;
    }
    float x0 = patch[(size_t)n * D + t];
    float x1 = patch[(size_t)n * D + t + 128];
    float x2 = patch[(size_t)n * D + t + 256];
    float s = x0 * x0 + x1 * x1 + x2 * x2;
    for (int o = 16; o > 0; o >>= 1) s += __shfl_down_sync(0xffffffffu, s, o);
    if ((t & 31) == 0) red[t >> 5] = s;
    __syncthreads();
    if (t == 0) bcast = red[0] + red[1] + red[2] + red[3];
    __syncthreads();
    float inv = 1.f / fmaxf(sqrtf(bcast), 1e-12f);
    float y0 = x0 * inv, y1 = x1 * inv, y2 = x2 * inv;
    g_patchN[(size_t)n * D + t]       = y0;
    g_patchN[(size_t)n * D + t + 128] = y1;
    g_patchN[(size_t)n * D + t + 256] = y2;
    float p = y0 * y0 + y1 * y1 + y2 * y2;
    for (int o = 16; o > 0; o >>= 1) p += __shfl_down_sync(0xffffffffu, p, o);
    if ((t & 31) == 0) red[t >> 5] = p;
    __syncthreads();
    if (t == 0) g_pn[n] = red[0] + red[1] + red[2] + red[3];
}

// ---------------- 2) gaussian kernel weights ----------------
__global__ void gk_kernel() {
    __shared__ float w[KS];
    int t = threadIdx.x;    // 64 threads
    if (t < KS) {
        float x = (float)(t - RAD);
        w[t] = expf(-0.5f * (x / 4.f) * (x / 4.f));
    }
    __syncthreads();
    if (t == 0) {
        float s = 0.f;
        for (int i = 0; i < KS; i++) s += w[i];
        for (int i = 0; i < KS; i++) g_kern[i] = w[i] / s;
    }
}

// ---------------- 3) per-row ||lib||^2 (warp per row, float4) ----------------
__global__ void ln_kernel(const float* __restrict__ lib) {
    int t = threadIdx.x, warp = t >> 5, lane = t & 31;
    long r = (long)blockIdx.x * 8 + warp;
    if (r >= MPAD) return;
    if (r >= M) { if (lane == 0) g_ln[r] = 1e30f; return; }
    const float4* row = (const float4*)(lib + (size_t)r * D);
    float s = 0.f;
#pragma unroll
    for (int j = 0; j < 3; j++) {
        float4 v = row[lane + 32 * j];
        s += v.x * v.x + v.y * v.y + v.z * v.z + v.w * v.w;
    }
    for (int o = 16; o > 0; o >>= 1) s += __shfl_down_sync(0xffffffffu, s, o);
    if (lane == 0) g_ln[r] = s;
}

// ---------------- 4) GEMM + fused per-tile min reduction ----------------
__global__ void __launch_bounds__(128) gemm_kernel(const float* __restrict__ lib) {
    __shared__ float As[KB][TN + 4];   // stride 68 floats: 16B-aligned rows
    __shared__ float Bs[KB][TM + 4];   // stride 132 floats: 16B-aligned rows
    int t = threadIdx.x;
    int tx = t & 15, ty = t >> 4;      // 16 x 8
    int n0 = blockIdx.x * TN;
    int mb = blockIdx.y;
    long m0 = (long)mb * TM;

    float acc[8][8];
#pragma unroll
    for (int i = 0; i < 8; i++)
#pragma unroll
        for (int j = 0; j < 8; j++) acc[i][j] = 0.f;

    for (int kt = 0; kt < NKT; kt++) {
        int k0 = kt * KB;
        // A tile: 64x32 floats = 512 float4, 4 per thread (coalesced)
#pragma unroll
        for (int i = 0; i < 4; i++) {
            int e = i * 128 + t;
            int n = e >> 3, f = e & 7;
            float4 v = *(const float4*)(g_patchN + (size_t)(n0 + n) * D + k0 + f * 4);
            As[f * 4 + 0][n] = v.x; As[f * 4 + 1][n] = v.y;
            As[f * 4 + 2][n] = v.z; As[f * 4 + 3][n] = v.w;
        }
        // B tile: 128x32 floats = 1024 float4, 8 per thread (coalesced)
#pragma unroll
        for (int i = 0; i < 8; i++) {
            int e = i * 128 + t;
            int m = e >> 3, f = e & 7;
            long gm = m0 + m;
            float4 v = (gm < M) ? *(const float4*)(lib + (size_t)gm * D + k0 + f * 4)
                                : make_float4(0.f, 0.f, 0.f, 0.f);
            Bs[f * 4 + 0][m] = v.x; Bs[f * 4 + 1][m] = v.y;
            Bs[f * 4 + 2][m] = v.z; Bs[f * 4 + 3][m] = v.w;
        }
        __syncthreads();
#pragma unroll 8
        for (int k = 0; k < KB; k++) {
            float4 a0 = *(const float4*)&As[k][ty * 8];
            float4 a1 = *(const float4*)&As[k][ty * 8 + 4];
            float4 b0 = *(const float4*)&Bs[k][tx * 4];
            float4 b1 = *(const float4*)&Bs[k][tx * 4 + 64];
            float av[8] = {a0.x, a0.y, a0.z, a0.w, a1.x, a1.y, a1.z, a1.w};
            float bw[8] = {b0.x, b0.y, b0.z, b0.w, b1.x, b1.y, b1.z, b1.w};
#pragma unroll
            for (int i = 0; i < 8; i++)
#pragma unroll
                for (int j = 0; j < 8; j++) acc[i][j] += av[i] * bw[j];
        }
        __syncthreads();
    }
    // epilogue: per-n min of (ln - 2*dot) over this block's 128 m columns
#pragma unroll
    for (int i = 0; i < 8; i++) {
        float bvv = 3.4e38f; int bii = 0x7fffffff;
#pragma unroll
        for (int j = 0; j < 8; j++) {
            long gm = m0 + ((j < 4) ? (tx * 4 + j) : (64 + tx * 4 + (j - 4)));
            float v = g_ln[gm] - 2.f * acc[i][j];
            int idx = (int)gm;
            if (lt_vi(v, idx, bvv, bii)) { bvv = v; bii = idx; }
        }
#pragma unroll
        for (int o = 8; o > 0; o >>= 1) {
            float ov = __shfl_down_sync(0xffffffffu, bvv, o, 16);
            int   oi = __shfl_down_sync(0xffffffffu, bii, o, 16);
            if (lt_vi(ov, oi, bvv, bii)) { bvv = ov; bii = oi; }
        }
        if (tx == 0) {
            int n = n0 + ty * 8 + i;
            g_pv[(size_t)n * MBY + mb] = bvv;
            g_pi[(size_t)n * MBY + mb] = bii;
        }
    }
}

// ---------------- 5) reduce partials -> min_val / min_idx per n ----------------
__global__ void reduce1_kernel() {
    int n = blockIdx.x, t = threadIdx.x;  // 256 threads
    float bv = 3.4e38f; int bi = 0x7fffffff;
    for (int b = t; b < MBY; b += 256) {
        float v = g_pv[(size_t)n * MBY + b];
        int i = g_pi[(size_t)n * MBY + b];
        if (lt_vi(v, i, bv, bi)) { bv = v; bi = i; }
    }
    __shared__ float sv[256]; __shared__ int si[256];
    sv[t] = bv; si[t] = bi;
    __syncthreads();
    for (int s = 128; s > 0; s >>= 1) {
        if (t < s && lt_vi(sv[t + s], si[t + s], sv[t], si[t])) {
            sv[t] = sv[t + s]; si[t] = si[t + s];
        }
        __syncthreads();
    }
    if (t == 0) {
        g_minval[n] = sqrtf(fmaxf(g_pn[n] + sv[0], 0.f));
        g_minidx[n] = si[0];
    }
}

// ---------------- 6) argmax over n; m_star; ||m_star||^2 ----------------
__global__ void reduce2_kernel(const float* __restrict__ lib) {
    int t = threadIdx.x;  // 256
    __shared__ float sv[256]; __shared__ int si[256];
    __shared__ int smstar;
    float bv = -3.4e38f; int bi = 0x7fffffff;
    for (int n = t; n < N_PATCH; n += 256) {
        float v = g_minval[n];
        if (v > bv || (v == bv && n < bi)) { bv = v; bi = n; }
    }
    sv[t] = bv; si[t] = bi;
    __syncthreads();
    for (int s = 128; s > 0; s >>= 1) {
        if (t < s) {
            if (sv[t + s] > sv[t] || (sv[t + s] == sv[t] && si[t + s] < si[t])) {
                sv[t] = sv[t + s]; si[t] = si[t + s];
            }
        }
        __syncthreads();
    }
    if (t == 0) {
        int sidx = si[0];
        g_sidx = sidx;
        g_sstar = sv[0];
        int ms = g_minidx[sidx];
        g_mstar = ms;
        smstar = ms;
    }
    __syncthreads();
    int ms = smstar;
    float p = 0.f;
    for (int c = t; c < D; c += 256) {
        float x = lib[(size_t)ms * D + c];
        p += x * x;
    }
    sv[t] = p; __syncthreads();
    for (int s = 128; s > 0; s >>= 1) { if (t < s) sv[t] += sv[t + s]; __syncthreads(); }
    if (t == 0) g_msn = sv[0];
}

// ---------------- 7) d_star = dist(lib, m_star) ----------------
__global__ void dstar_kernel(const float* __restrict__ lib) {
    __shared__ float4 msv[96];
    int t = threadIdx.x;
    int mi = g_mstar;
    if (t < 96) msv[t] = *((const float4*)(lib + (size_t)mi * D) + t);
    __syncthreads();
    int warp = t >> 5, lane = t & 31;
    long r = (long)blockIdx.x * 8 + warp;
    if (r >= M) return;
    const float4* row = (const float4*)(lib + (size_t)r * D);
    float s = 0.f;
#pragma unroll
    for (int j = 0; j < 3; j++) {
        float4 v = row[lane + 32 * j];
        float4 w = msv[lane + 32 * j];
        s += v.x * w.x + v.y * w.y + v.z * w.z + v.w * w.w;
    }
    for (int o = 16; o > 0; o >>= 1) s += __shfl_down_sync(0xffffffffu, s, o);
    if (lane == 0) g_dstar[r] = sqrtf(fmaxf(g_ln[r] + g_msn - 2.f * s, 0.f));
}

// ---------------- 8) top-5 smallest d_star ----------------
__global__ void top5_kernel() {
    int t = threadIdx.x;  // 256
    float bv[5]; int bi[5];
#pragma unroll
    for (int k = 0; k < 5; k++) { bv[k] = 3.4e38f; bi[k] = 0x7fffffff; }
    for (int m = t; m < M; m += 256) {
        float v = g_dstar[m];
        if (lt_vi(v, m, bv[4], bi[4])) {
            bv[4] = v; bi[4] = m;
#pragma unroll
            for (int k = 4; k > 0; k--) {
                if (lt_vi(bv[k], bi[k], bv[k - 1], bi[k - 1])) {
                    float tv = bv[k]; bv[k] = bv[k - 1]; bv[k - 1] = tv;
                    int ti = bi[k]; bi[k] = bi[k - 1]; bi[k - 1] = ti;
                }
            }
        }
    }
    __shared__ float sv[256][5]; __shared__ int si[256][5];
    __shared__ float rv[256]; __shared__ int ri[256]; __shared__ int rk[256];
#pragma unroll
    for (int k = 0; k < 5; k++) { sv[t][k] = bv[k]; si[t][k] = bi[k]; }
    __syncthreads();
    for (int sel = 0; sel < 5; sel++) {
        float cv = 3.4e38f; int ci = 0x7fffffff; int ck = 0;
#pragma unroll
        for (int k = 0; k < 5; k++)
            if (lt_vi(sv[t][k], si[t][k], cv, ci)) { cv = sv[t][k]; ci = si[t][k]; ck = k; }
        rv[t] = cv; ri[t] = ci; rk[t] = ck * 256 + t;
        __syncthreads();
        for (int s = 128; s > 0; s >>= 1) {
            if (t < s && lt_vi(rv[t + s], ri[t + s], rv[t], ri[t])) {
                rv[t] = rv[t + s]; ri[t] = ri[t + s]; rk[t] = rk[t + s];
            }
            __syncthreads();
        }
        if (t == 0) g_nn[sel] = ri[0];
        int owner = rk[0];
        __syncthreads();
        if (t == (owner & 255)) { sv[t][owner >> 8] = 3.4e38f; si[t][owner >> 8] = 0x7fffffff; }
        __syncthreads();
    }
}

// ---------------- 9) scalar s ----------------
__global__ void scalar_kernel(const float* __restrict__ lib, float* __restrict__ out) {
    __shared__ float dd[6];
    __shared__ int tgt[6];
    int t = threadIdx.x, warp = t >> 5, lane = t & 31;  // 192 threads = 6 warps
    if (t < 5) tgt[t] = g_nn[t];
    if (t == 5) tgt[5] = g_mstar;
    __syncthreads();
    {
        long rm = tgt[warp];
        const float* p = g_patchN + (size_t)g_sidx * D;
        const float* q = lib + (size_t)rm * D;
        float s = 0.f;
        for (int c = lane; c < D; c += 32) {
            float d = p[c] - q[c];
            s += d * d;
        }
        for (int o = 16; o > 0; o >>= 1) s += __shfl_down_sync(0xffffffffu, s, o);
        if (lane == 0) dd[warp] = sqrtf(s);
    }
    __syncthreads();
    if (t == 0) {
        float den = 0.f;
        for (int k = 0; k < 5; k++) den += expf(dd[k]);
        float num = expf(dd[5]);
        out[0] = (1.f - num / den) * g_sstar;
    }
}

// ---------------- 10) bilinear resize 26x26 -> 224x224 (half-pixel) ----------------
__global__ void resize_kernel() {
    int idx = blockIdx.x * 256 + threadIdx.x;
    if (idx >= IMG * IMG) return;
    int y = idx / IMG, x = idx % IMG;
    const float scale = 26.f / 224.f;
    float fy = (y + 0.5f) * scale - 0.5f;
    float fx = (x + 0.5f) * scale - 0.5f;
    int y0 = (int)floorf(fy), x0 = (int)floorf(fx);
    float wy = fy - (float)y0, wx = fx - (float)x0;
    int y0c = min(max(y0, 0), 25), y1c = min(max(y0 + 1, 0), 25);
    int x0c = min(max(x0, 0), 25), x1c = min(max(x0 + 1, 0), 25);
    float v00 = g_minval[y0c * 26 + x0c], v01 = g_minval[y0c * 26 + x1c];
    float v10 = g_minval[y1c * 26 + x0c], v11 = g_minval[y1c * 26 + x1c];
    g_rmap[idx] = (1.f - wy) * ((1.f - wx) * v00 + wx * v01)
                + wy * ((1.f - wx) * v10 + wx * v11);
}

__device__ __forceinline__ int reflect_idx(int i) {
    if (i < 0) return -i;
    if (i > IMG - 1) return 2 * (IMG - 1) - i;
    return i;
}

// ---------------- 11) vertical then horizontal blur (reflect) ----------------
__global__ void blurv_kernel() {
    __shared__ float kw[KS];
    int t = threadIdx.x;
    if (t < KS) kw[t] = g_kern[t];
    __syncthreads();
    int idx = blockIdx.x * 256 + t;
    if (idx >= IMG * IMG) return;
    int y = idx / IMG, x = idx % IMG;
    float s = 0.f;
#pragma unroll
    for (int d = 0; d < KS; d++) {
        int yy = reflect_idx(y + d - RAD);
        s += kw[d] * g_rmap[yy * IMG + x];
    }
    g_tmap[idx] = s;
}

__global__ void blurh_kernel(float* __restrict__ out) {
    __shared__ float kw[KS];
    int t = threadIdx.x;
    if (t < KS) kw[t] = g_kern[t];
    __syncthreads();
    int idx = blockIdx.x * 256 + t;
    if (idx >= IMG * IMG) return;
    int y = idx / IMG, x = idx % IMG;
    float s = 0.f;
#pragma unroll
    for (int d = 0; d < KS; d++) {
        int xx = reflect_idx(x + d - RAD);
        s += kw[d] * g_tmap[y * IMG + xx];
    }
    out[1 + idx] = s;
}

// ---------------- launch ----------------
extern "C" void kernel_launch(void* const* d_in, const int* in_sizes, int n_in,
                              void* d_out, int out_size) {
    const float* patch = (const float*)d_in[0];
    const float* lib   = (const float*)d_in[1];
    if (n_in >= 2 && in_sizes[0] > in_sizes[1]) {  // defensive: patch is the small one
        const float* tmp = patch; patch = lib; lib = tmp;
    }
    float* out = (float*)d_out;

    prep_kernel<<<NPAD, 128>>>(patch);
    gk_kernel<<<1, 64>>>();
    ln_kernel<<<MPAD / 8, 256>>>(lib);
    dim3 gg(NBX, MBY);
    gemm_kernel<<<gg, 128>>>(lib);
    reduce1_kernel<<<N_PATCH, 256>>>();
    reduce2_kernel<<<1, 256>>>(lib);
    dstar_kernel<<<M / 8, 256>>>(lib);
    top5_kernel<<<1, 256>>>();
    scalar_kernel<<<1, 192>>>(lib, out);
    resize_kernel<<<196, 256>>>();
    blurv_kernel<<<196, 256>>>();
    blurh_kernel<<<196, 256>>>(out);
}